// round 2
// baseline (speedup 1.0000x reference)
#include <cuda_runtime.h>
#include <cstdint>

#define Bsz 64
#define Ssz 1024
#define Dsz 128
#define Hsz 20
#define Gsz 80

// scratch (static device globals: no allocation)
__device__ float g_GI[Bsz * Ssz * Gsz];   // pre-activations from x-part, bias included
__device__ float g_MU[Bsz * Ssz];
__device__ float g_SIG[Bsz * Ssz];

// ---------------- fast math helpers ----------------
__device__ __forceinline__ float fexp2(float x) {
    float r; asm("ex2.approx.ftz.f32 %0, %1;" : "=f"(r) : "f"(x)); return r;
}
__device__ __forceinline__ float frcp(float x) {
    float r; asm("rcp.approx.ftz.f32 %0, %1;" : "=f"(r) : "f"(x)); return r;
}
__device__ __forceinline__ float fsigm(float x) {
    // 1/(1+e^-x)
    return frcp(1.0f + fexp2(-1.442695041f * x));
}
__device__ __forceinline__ float ftanh(float x) {
    x = fminf(fmaxf(x, -10.0f), 10.0f);
    float e = fexp2(2.885390082f * x);   // e^(2x)
    return (e - 1.0f) * frcp(e + 1.0f);
}

// ================= Kernel 1: GI = x @ W_ih^T + (b_ih+b_hh) =================
// CTA: 64 rows (b*S+t flattened) x 80 gates. 256 threads, per-thread 4x5 tile.
__global__ __launch_bounds__(256) void k1_gi(
    const float* __restrict__ x,
    const float* __restrict__ Wih,
    const float* __restrict__ bih,
    const float* __restrict__ bhh)
{
    __shared__ float ws[128 * 80];   // ws[k*80+g] = Wih[g*128+k] (transposed)
    __shared__ float xs[16 * 64];    // xs[kk*64+r]
    __shared__ float bs[80];

    int tid = threadIdx.x;
    // stage W transposed (one time)
    for (int i = tid; i < Gsz * 32; i += 256) {
        int g = i >> 5, k4 = (i & 31) << 2;
        float4 v = *(const float4*)(Wih + g * 128 + k4);
        ws[(k4 + 0) * 80 + g] = v.x;
        ws[(k4 + 1) * 80 + g] = v.y;
        ws[(k4 + 2) * 80 + g] = v.z;
        ws[(k4 + 3) * 80 + g] = v.w;
    }
    if (tid < 80) bs[tid] = bih[tid] + bhh[tid];

    int row0 = blockIdx.x * 64;
    int ty = tid >> 4, tx = tid & 15;          // ty:0..15 rows, tx:0..15 gate-groups
    float acc[4][5];
#pragma unroll
    for (int r = 0; r < 4; r++)
#pragma unroll
        for (int c = 0; c < 5; c++) acc[r][c] = 0.0f;

    for (int kc = 0; kc < 8; kc++) {
        __syncthreads();
        {   // stage 64 rows x 16 k
            int r = tid >> 2, kk = (tid & 3) << 2;
            float4 v = *(const float4*)(x + (size_t)(row0 + r) * 128 + kc * 16 + kk);
            xs[(kk + 0) * 64 + r] = v.x;
            xs[(kk + 1) * 64 + r] = v.y;
            xs[(kk + 2) * 64 + r] = v.z;
            xs[(kk + 3) * 64 + r] = v.w;
        }
        __syncthreads();
#pragma unroll
        for (int kk = 0; kk < 16; kk++) {
            float4 xa = *(float4*)&xs[kk * 64 + ty * 4];
            const float* wp = &ws[(kc * 16 + kk) * 80 + tx * 5];
            float w0 = wp[0], w1 = wp[1], w2 = wp[2], w3 = wp[3], w4 = wp[4];
            acc[0][0] = fmaf(xa.x, w0, acc[0][0]);
            acc[0][1] = fmaf(xa.x, w1, acc[0][1]);
            acc[0][2] = fmaf(xa.x, w2, acc[0][2]);
            acc[0][3] = fmaf(xa.x, w3, acc[0][3]);
            acc[0][4] = fmaf(xa.x, w4, acc[0][4]);
            acc[1][0] = fmaf(xa.y, w0, acc[1][0]);
            acc[1][1] = fmaf(xa.y, w1, acc[1][1]);
            acc[1][2] = fmaf(xa.y, w2, acc[1][2]);
            acc[1][3] = fmaf(xa.y, w3, acc[1][3]);
            acc[1][4] = fmaf(xa.y, w4, acc[1][4]);
            acc[2][0] = fmaf(xa.z, w0, acc[2][0]);
            acc[2][1] = fmaf(xa.z, w1, acc[2][1]);
            acc[2][2] = fmaf(xa.z, w2, acc[2][2]);
            acc[2][3] = fmaf(xa.z, w3, acc[2][3]);
            acc[2][4] = fmaf(xa.z, w4, acc[2][4]);
            acc[3][0] = fmaf(xa.w, w0, acc[3][0]);
            acc[3][1] = fmaf(xa.w, w1, acc[3][1]);
            acc[3][2] = fmaf(xa.w, w2, acc[3][2]);
            acc[3][3] = fmaf(xa.w, w3, acc[3][3]);
            acc[3][4] = fmaf(xa.w, w4, acc[3][4]);
        }
    }
    float* go = g_GI + (size_t)row0 * 80;
#pragma unroll
    for (int r = 0; r < 4; r++) {
        int row = ty * 4 + r;
#pragma unroll
        for (int c = 0; c < 5; c++)
            go[(size_t)row * 80 + tx * 5 + c] = acc[r][c] + bs[tx * 5 + c];
    }
}

// ================= Kernel 2: LSTM scan + heads + mu scan =================
// One CTA per batch. 128 threads: 0..79 gate-per-thread, 80..82 heads.
__global__ __launch_bounds__(128) void k2_lstm(
    const float* __restrict__ Whh,
    const float* __restrict__ Wmu, const float* __restrict__ bmu,
    const float* __restrict__ Wsig, const float* __restrict__ bsig)
{
    __shared__ __align__(16) float hs[20];
    __shared__ float garr[80];
    __shared__ float Ab[1024];
    __shared__ float Cb[1024];

    int b = blockIdx.x;
    int tid = threadIdx.x;

    float wa[20], wb2[20];
#pragma unroll
    for (int k = 0; k < 20; k++) { wa[k] = 0.0f; wb2[k] = 0.0f; }
    if (tid < 80) {
#pragma unroll
        for (int k = 0; k < 20; k++) wa[k] = Whh[tid * 20 + k];
    } else if (tid == 80) {
#pragma unroll
        for (int k = 0; k < 20; k++) wa[k] = Wmu[k];            // row 0 -> a
    } else if (tid == 81) {
#pragma unroll
        for (int k = 0; k < 20; k++) { wa[k] = Wmu[20 + k]; wb2[k] = Wmu[40 + k]; }
    } else if (tid == 82) {
#pragma unroll
        for (int k = 0; k < 20; k++) wa[k] = Wsig[k];
    }
    float bm0 = bmu[0], bm1 = bmu[1], bm2 = bmu[2], bsg = bsig[0];

    if (tid < 20) hs[tid] = 0.0f;
    float c = 0.0f;
    __syncthreads();

    const float* gip = g_GI + (size_t)b * Ssz * Gsz;
    float gi = (tid < 80) ? gip[tid] : 0.0f;
    int type = tid / 20;

    for (int t = 0; t < 1024; t++) {
        float gi_n = 0.0f;
        if (tid < 80 && t + 1 < 1024) gi_n = gip[(size_t)(t + 1) * 80 + tid];

        float4 h0 = *(float4*)&hs[0];
        float4 h1 = *(float4*)&hs[4];
        float4 h2 = *(float4*)&hs[8];
        float4 h3 = *(float4*)&hs[12];
        float4 h4 = *(float4*)&hs[16];

        if (tid < 80) {
            float a0 = gi, a1 = 0.f, a2 = 0.f, a3 = 0.f;
            a0 = fmaf(wa[0],  h0.x, a0); a1 = fmaf(wa[1],  h0.y, a1);
            a2 = fmaf(wa[2],  h0.z, a2); a3 = fmaf(wa[3],  h0.w, a3);
            a0 = fmaf(wa[4],  h1.x, a0); a1 = fmaf(wa[5],  h1.y, a1);
            a2 = fmaf(wa[6],  h1.z, a2); a3 = fmaf(wa[7],  h1.w, a3);
            a0 = fmaf(wa[8],  h2.x, a0); a1 = fmaf(wa[9],  h2.y, a1);
            a2 = fmaf(wa[10], h2.z, a2); a3 = fmaf(wa[11], h2.w, a3);
            a0 = fmaf(wa[12], h3.x, a0); a1 = fmaf(wa[13], h3.y, a1);
            a2 = fmaf(wa[14], h3.z, a2); a3 = fmaf(wa[15], h3.w, a3);
            a0 = fmaf(wa[16], h4.x, a0); a1 = fmaf(wa[17], h4.y, a1);
            a2 = fmaf(wa[18], h4.z, a2); a3 = fmaf(wa[19], h4.w, a3);
            float pre = (a0 + a1) + (a2 + a3);
            garr[tid] = (type == 2) ? ftanh(pre) : fsigm(pre);
        } else if (t > 0) {
            if (tid == 80) {
                float d = bm0;
                d += wa[0]*h0.x + wa[1]*h0.y + wa[2]*h0.z + wa[3]*h0.w;
                d += wa[4]*h1.x + wa[5]*h1.y + wa[6]*h1.z + wa[7]*h1.w;
                d += wa[8]*h2.x + wa[9]*h2.y + wa[10]*h2.z + wa[11]*h2.w;
                d += wa[12]*h3.x + wa[13]*h3.y + wa[14]*h3.z + wa[15]*h3.w;
                d += wa[16]*h4.x + wa[17]*h4.y + wa[18]*h4.z + wa[19]*h4.w;
                Ab[t - 1] = fmaxf(d, 0.0f);
            } else if (tid == 81) {
                float d1 = bm1, d2 = bm2;
                d1 += wa[0]*h0.x + wa[1]*h0.y + wa[2]*h0.z + wa[3]*h0.w;
                d1 += wa[4]*h1.x + wa[5]*h1.y + wa[6]*h1.z + wa[7]*h1.w;
                d1 += wa[8]*h2.x + wa[9]*h2.y + wa[10]*h2.z + wa[11]*h2.w;
                d1 += wa[12]*h3.x + wa[13]*h3.y + wa[14]*h3.z + wa[15]*h3.w;
                d1 += wa[16]*h4.x + wa[17]*h4.y + wa[18]*h4.z + wa[19]*h4.w;
                d2 += wb2[0]*h0.x + wb2[1]*h0.y + wb2[2]*h0.z + wb2[3]*h0.w;
                d2 += wb2[4]*h1.x + wb2[5]*h1.y + wb2[6]*h1.z + wb2[7]*h1.w;
                d2 += wb2[8]*h2.x + wb2[9]*h2.y + wb2[10]*h2.z + wb2[11]*h2.w;
                d2 += wb2[12]*h3.x + wb2[13]*h3.y + wb2[14]*h3.z + wb2[15]*h3.w;
                d2 += wb2[16]*h4.x + wb2[17]*h4.y + wb2[18]*h4.z + wb2[19]*h4.w;
                Cb[t - 1] = (fmaxf(d1, 0.0f) + fmaxf(d2, 0.0f) * (float)t) * (1.0f / 1024.0f);
            } else if (tid == 82) {
                float d = bsg;
                d += wa[0]*h0.x + wa[1]*h0.y + wa[2]*h0.z + wa[3]*h0.w;
                d += wa[4]*h1.x + wa[5]*h1.y + wa[6]*h1.z + wa[7]*h1.w;
                d += wa[8]*h2.x + wa[9]*h2.y + wa[10]*h2.z + wa[11]*h2.w;
                d += wa[12]*h3.x + wa[13]*h3.y + wa[14]*h3.z + wa[15]*h3.w;
                d += wa[16]*h4.x + wa[17]*h4.y + wa[18]*h4.z + wa[19]*h4.w;
                g_SIG[(size_t)b * Ssz + (t - 1)] = fsigm(d);
            }
        }
        __syncthreads();
        if (tid < 20) {
            float cv = fmaf(garr[20 + tid], c, garr[tid] * garr[40 + tid]);
            c = cv;
            hs[tid] = garr[60 + tid] * ftanh(cv);
        }
        gi = gi_n;
        __syncthreads();
    }

    // final heads for t=1023 with final h
    {
        float4 h0 = *(float4*)&hs[0];
        float4 h1 = *(float4*)&hs[4];
        float4 h2 = *(float4*)&hs[8];
        float4 h3 = *(float4*)&hs[12];
        float4 h4 = *(float4*)&hs[16];
        if (tid == 80) {
            float d = bm0;
            d += wa[0]*h0.x + wa[1]*h0.y + wa[2]*h0.z + wa[3]*h0.w;
            d += wa[4]*h1.x + wa[5]*h1.y + wa[6]*h1.z + wa[7]*h1.w;
            d += wa[8]*h2.x + wa[9]*h2.y + wa[10]*h2.z + wa[11]*h2.w;
            d += wa[12]*h3.x + wa[13]*h3.y + wa[14]*h3.z + wa[15]*h3.w;
            d += wa[16]*h4.x + wa[17]*h4.y + wa[18]*h4.z + wa[19]*h4.w;
            Ab[1023] = fmaxf(d, 0.0f);
        } else if (tid == 81) {
            float d1 = bm1, d2 = bm2;
            d1 += wa[0]*h0.x + wa[1]*h0.y + wa[2]*h0.z + wa[3]*h0.w;
            d1 += wa[4]*h1.x + wa[5]*h1.y + wa[6]*h1.z + wa[7]*h1.w;
            d1 += wa[8]*h2.x + wa[9]*h2.y + wa[10]*h2.z + wa[11]*h2.w;
            d1 += wa[12]*h3.x + wa[13]*h3.y + wa[14]*h3.z + wa[15]*h3.w;
            d1 += wa[16]*h4.x + wa[17]*h4.y + wa[18]*h4.z + wa[19]*h4.w;
            d2 += wb2[0]*h0.x + wb2[1]*h0.y + wb2[2]*h0.z + wb2[3]*h0.w;
            d2 += wb2[4]*h1.x + wb2[5]*h1.y + wb2[6]*h1.z + wb2[7]*h1.w;
            d2 += wb2[8]*h2.x + wb2[9]*h2.y + wb2[10]*h2.z + wb2[11]*h2.w;
            d2 += wb2[12]*h3.x + wb2[13]*h3.y + wb2[14]*h3.z + wb2[15]*h3.w;
            d2 += wb2[16]*h4.x + wb2[17]*h4.y + wb2[18]*h4.z + wb2[19]*h4.w;
            Cb[1023] = (fmaxf(d1, 0.0f) + fmaxf(d2, 0.0f) * 1024.0f) * (1.0f / 1024.0f);
        } else if (tid == 82) {
            float d = bsg;
            d += wa[0]*h0.x + wa[1]*h0.y + wa[2]*h0.z + wa[3]*h0.w;
            d += wa[4]*h1.x + wa[5]*h1.y + wa[6]*h1.z + wa[7]*h1.w;
            d += wa[8]*h2.x + wa[9]*h2.y + wa[10]*h2.z + wa[11]*h2.w;
            d += wa[12]*h3.x + wa[13]*h3.y + wa[14]*h3.z + wa[15]*h3.w;
            d += wa[16]*h4.x + wa[17]*h4.y + wa[18]*h4.z + wa[19]*h4.w;
            g_SIG[(size_t)b * Ssz + 1023] = fsigm(d);
        }
    }
    __syncthreads();
    if (tid == 0) {
        float mu = 0.0f;
        float* mo = g_MU + (size_t)b * Ssz;
        for (int j = 0; j < 1024; j++) {
            mu = fmaf(Ab[j], mu, Cb[j]);
            mo[j] = mu;
        }
    }
}

// ================= Kernel 3: positional attention GEMM =================
// CTA: one (b, j-tile of 128). 256 threads, 8x8 register tile.
__global__ __launch_bounds__(256, 2) void k3_attn(
    const float* __restrict__ x, float* __restrict__ out)
{
    __shared__ float xs[32 * 128];   // xs[t][d]
    __shared__ float wbuf[32 * 128]; // wbuf[t][j]
    __shared__ float muv[128], i2s[128], invj[128], nrm[128];

    int b = blockIdx.y;
    int jt = 7 - blockIdx.x;   // big tiles first
    int j0 = jt * 128;
    int tid = threadIdx.x;

    if (tid < 128) {
        int j = j0 + tid;
        float mu = g_MU[(size_t)b * Ssz + j];
        float sg = g_SIG[(size_t)b * Ssz + j];
        muv[tid] = mu;
        i2s[tid] = -1.442695041f / (2.0f * sg * sg);
        invj[tid] = 1.0f / (float)(j + 1);
        nrm[tid] = 0.0f;
    }
    __syncthreads();

    int ty = tid >> 4, tx = tid & 15;
    int jcol = tid & 127, part = tid >> 7;
    float mu_r = muv[jcol], i2s_r = i2s[jcol], invj_r = invj[jcol];
    int jabs = j0 + jcol;

    float acc[8][8];
#pragma unroll
    for (int i = 0; i < 8; i++)
#pragma unroll
        for (int j = 0; j < 8; j++) acc[i][j] = 0.0f;

    const float* xb = x + (size_t)b * Ssz * Dsz;
    int nch = (jt + 1) * 4;

    for (int tc = 0; tc < nch; tc++) {
        // stage x chunk: 32 t x 128 d
#pragma unroll
        for (int q = 0; q < 4; q++) {
            int f4 = tid + 256 * q;
            int tr = f4 >> 5, dc = (f4 & 31) << 2;
            *(float4*)&xs[tr * 128 + dc] =
                *(const float4*)(xb + (size_t)(tc * 32 + tr) * 128 + dc);
        }
        // compute weight chunk: each thread 16 t's for its j column
        float na = 0.0f;
        int tbase = part * 16;
#pragma unroll
        for (int tt = 0; tt < 16; tt++) {
            int t = tc * 32 + tbase + tt;
            float w = 0.0f;
            if (t <= jabs) {
                float r = fmaf((float)t, invj_r, -mu_r);
                w = fexp2(r * r * i2s_r);
            }
            wbuf[(tbase + tt) * 128 + jcol] = w;
            na = fmaf(w, w, na);
        }
        atomicAdd(&nrm[jcol], na);
        __syncthreads();

#pragma unroll 8
        for (int kk = 0; kk < 32; kk++) {
            float a[8], bv[8];
            float4 t0 = *(float4*)&wbuf[kk * 128 + ty * 4];
            float4 t1 = *(float4*)&wbuf[kk * 128 + 64 + ty * 4];
            a[0] = t0.x; a[1] = t0.y; a[2] = t0.z; a[3] = t0.w;
            a[4] = t1.x; a[5] = t1.y; a[6] = t1.z; a[7] = t1.w;
            float4 u0 = *(float4*)&xs[kk * 128 + tx * 4];
            float4 u1 = *(float4*)&xs[kk * 128 + 64 + tx * 4];
            bv[0] = u0.x; bv[1] = u0.y; bv[2] = u0.z; bv[3] = u0.w;
            bv[4] = u1.x; bv[5] = u1.y; bv[6] = u1.z; bv[7] = u1.w;
#pragma unroll
            for (int i = 0; i < 8; i++)
#pragma unroll
                for (int j = 0; j < 8; j++)
                    acc[i][j] = fmaf(a[i], bv[j], acc[i][j]);
        }
        __syncthreads();
    }
    __syncthreads();   // nrm fully accumulated before epilogue reads

    // epilogue: normalize rows and store
#pragma unroll
    for (int ri = 0; ri < 8; ri++) {
        int jrel = (ri < 4) ? (ty * 4 + ri) : (64 + ty * 4 + (ri - 4));
        float n = nrm[jrel];
        float s = fmaxf(sqrtf(n), 1e-12f);
        float inv = 1.0f / s;
        int j = j0 + jrel;
        float* op = out + ((size_t)b * Ssz + j) * Dsz;
        float4 v0, v1;
        v0.x = acc[ri][0] * inv; v0.y = acc[ri][1] * inv;
        v0.z = acc[ri][2] * inv; v0.w = acc[ri][3] * inv;
        v1.x = acc[ri][4] * inv; v1.y = acc[ri][5] * inv;
        v1.z = acc[ri][6] * inv; v1.w = acc[ri][7] * inv;
        *(float4*)(op + tx * 4) = v0;
        *(float4*)(op + 64 + tx * 4) = v1;
    }
}

// ================= launcher =================
extern "C" void kernel_launch(void* const* d_in, const int* in_sizes, int n_in,
                              void* d_out, int out_size)
{
    const float* x    = (const float*)d_in[0];
    const float* Wih  = (const float*)d_in[1];
    const float* Whh  = (const float*)d_in[2];
    const float* bih  = (const float*)d_in[3];
    const float* bhh  = (const float*)d_in[4];
    const float* Wmu  = (const float*)d_in[5];
    const float* bmu  = (const float*)d_in[6];
    const float* Wsig = (const float*)d_in[7];
    const float* bsig = (const float*)d_in[8];
    float* out = (float*)d_out;

    k1_gi<<<(Bsz * Ssz) / 64, 256>>>(x, Wih, bih, bhh);
    k2_lstm<<<Bsz, 128>>>(Whh, Wmu, bmu, Wsig, bsig);
    dim3 g3(8, Bsz);
    k3_attn<<<g3, 256>>>(x, out);
}

// round 3
// speedup vs baseline: 1.1039x; 1.1039x over previous
#include <cuda_runtime.h>
#include <cstdint>

#define Bsz 64
#define Ssz 1024
#define Dsz 128
#define Hsz 20
#define Gsz 80

// scratch (static device globals: no allocation)
// g_GI layout is PERMUTED: g_GI[b][t][u*4 + type] = preact of gate (type*20+u)
// so one lane's (i,f,g,o) for unit u is a contiguous float4.
__device__ float g_GI[Bsz * Ssz * Gsz];
__device__ float g_MU[Bsz * Ssz];
__device__ float g_SIG[Bsz * Ssz];

// ---------------- fast math helpers ----------------
__device__ __forceinline__ float fexp2(float x) {
    float r; asm("ex2.approx.ftz.f32 %0, %1;" : "=f"(r) : "f"(x)); return r;
}
__device__ __forceinline__ float frcp(float x) {
    float r; asm("rcp.approx.ftz.f32 %0, %1;" : "=f"(r) : "f"(x)); return r;
}
__device__ __forceinline__ float fsigm(float x) {
    return frcp(1.0f + fexp2(-1.442695041f * x));
}
__device__ __forceinline__ float ftanh(float x) {
    x = fminf(fmaxf(x, -10.0f), 10.0f);
    float e = fexp2(2.885390082f * x);   // e^(2x)
    return (e - 1.0f) * frcp(e + 1.0f);
}

// ================= Kernel 1: GI = x @ W_ih^T + (b_ih+b_hh), permuted =================
// CTA: 64 rows x 80 gates. 320 threads (ty 0..15 row-quads, tx 0..19 unit),
// per-thread 4x4 tile, float4 LDS on both operands, float4 permuted stores.
__global__ __launch_bounds__(320) void k1_gi(
    const float* __restrict__ x,
    const float* __restrict__ Wih,
    const float* __restrict__ bih,
    const float* __restrict__ bhh)
{
    __shared__ __align__(16) float ws[128 * 80]; // ws[k*80 + u*4+type] = Wih[(type*20+u)*128 + k]
    __shared__ __align__(16) float xs[16 * 64];  // xs[kk*64 + r]
    __shared__ __align__(16) float bs[80];       // permuted bias

    int tid = threadIdx.x;
    // stage W transposed + gate-permuted (one time)
    for (int i = tid; i < Gsz * 32; i += 320) {
        int g = i >> 5, k4 = (i & 31) << 2;
        int p = (g % 20) * 4 + (g / 20);
        float4 v = *(const float4*)(Wih + g * 128 + k4);
        ws[(k4 + 0) * 80 + p] = v.x;
        ws[(k4 + 1) * 80 + p] = v.y;
        ws[(k4 + 2) * 80 + p] = v.z;
        ws[(k4 + 3) * 80 + p] = v.w;
    }
    if (tid < 80) {
        int p = (tid % 20) * 4 + (tid / 20);
        bs[p] = bih[tid] + bhh[tid];
    }

    int row0 = blockIdx.x * 64;
    int tx = tid % 20, ty = tid / 20;   // tx: unit (4 permuted gate cols), ty: row-quad
    float acc[4][4];
#pragma unroll
    for (int r = 0; r < 4; r++)
#pragma unroll
        for (int c = 0; c < 4; c++) acc[r][c] = 0.0f;

    for (int kc = 0; kc < 8; kc++) {
        __syncthreads();
        if (tid < 256) {   // stage 64 rows x 16 k
            int r = tid >> 2, kk = (tid & 3) << 2;
            float4 v = *(const float4*)(x + (size_t)(row0 + r) * 128 + kc * 16 + kk);
            xs[(kk + 0) * 64 + r] = v.x;
            xs[(kk + 1) * 64 + r] = v.y;
            xs[(kk + 2) * 64 + r] = v.z;
            xs[(kk + 3) * 64 + r] = v.w;
        }
        __syncthreads();
#pragma unroll
        for (int kk = 0; kk < 16; kk++) {
            float4 xa = *(float4*)&xs[kk * 64 + ty * 4];
            float4 wv = *(float4*)&ws[(kc * 16 + kk) * 80 + tx * 4];
            acc[0][0] = fmaf(xa.x, wv.x, acc[0][0]);
            acc[0][1] = fmaf(xa.x, wv.y, acc[0][1]);
            acc[0][2] = fmaf(xa.x, wv.z, acc[0][2]);
            acc[0][3] = fmaf(xa.x, wv.w, acc[0][3]);
            acc[1][0] = fmaf(xa.y, wv.x, acc[1][0]);
            acc[1][1] = fmaf(xa.y, wv.y, acc[1][1]);
            acc[1][2] = fmaf(xa.y, wv.z, acc[1][2]);
            acc[1][3] = fmaf(xa.y, wv.w, acc[1][3]);
            acc[2][0] = fmaf(xa.z, wv.x, acc[2][0]);
            acc[2][1] = fmaf(xa.z, wv.y, acc[2][1]);
            acc[2][2] = fmaf(xa.z, wv.z, acc[2][2]);
            acc[2][3] = fmaf(xa.z, wv.w, acc[2][3]);
            acc[3][0] = fmaf(xa.w, wv.x, acc[3][0]);
            acc[3][1] = fmaf(xa.w, wv.y, acc[3][1]);
            acc[3][2] = fmaf(xa.w, wv.z, acc[3][2]);
            acc[3][3] = fmaf(xa.w, wv.w, acc[3][3]);
        }
    }
    float4 bb = *(float4*)&bs[tx * 4];
    float* go = g_GI + (size_t)row0 * 80;
#pragma unroll
    for (int r = 0; r < 4; r++) {
        int row = ty * 4 + r;
        float4 o;
        o.x = acc[r][0] + bb.x;
        o.y = acc[r][1] + bb.y;
        o.z = acc[r][2] + bb.z;
        o.w = acc[r][3] + bb.w;
        *(float4*)&go[(size_t)row * 80 + tx * 4] = o;
    }
}

// ================= Kernel 2: warp-per-batch shuffle LSTM + heads + mu scan ========
// 64 CTAs x 32 threads. Lane l<20 owns hidden unit l (all 4 gate rows in regs);
// lanes 20..22 compute the mu/sigma heads from the same shuffled h.
__global__ __launch_bounds__(32) void k2_lstm(
    const float* __restrict__ Whh,
    const float* __restrict__ Wmu, const float* __restrict__ bmu,
    const float* __restrict__ Wsig, const float* __restrict__ bsig)
{
    __shared__ float Ab[1024];
    __shared__ float Cb[1024];

    int b = blockIdx.x;
    int l = threadIdx.x;
    bool isg = (l < 20);

    float wI[20], wF[20], wG[20], wO[20];
#pragma unroll
    for (int k = 0; k < 20; k++) { wI[k] = 0.f; wF[k] = 0.f; wG[k] = 0.f; wO[k] = 0.f; }
    if (isg) {
#pragma unroll
        for (int k = 0; k < 20; k++) {
            wI[k] = Whh[l * 20 + k];
            wF[k] = Whh[(20 + l) * 20 + k];
            wG[k] = Whh[(40 + l) * 20 + k];
            wO[k] = Whh[(60 + l) * 20 + k];
        }
    } else if (l == 20) {
#pragma unroll
        for (int k = 0; k < 20; k++) wI[k] = Wmu[k];
    } else if (l == 21) {
#pragma unroll
        for (int k = 0; k < 20; k++) { wI[k] = Wmu[20 + k]; wF[k] = Wmu[40 + k]; }
    } else if (l == 22) {
#pragma unroll
        for (int k = 0; k < 20; k++) wI[k] = Wsig[k];
    }
    float bm0 = bmu[0], bm1 = bmu[1], bm2 = bmu[2], bsg = bsig[0];

    float h = 0.0f, c = 0.0f;
    const float* gp = g_GI + (size_t)b * Ssz * Gsz + l * 4;

    float4 buf0 = make_float4(0.f, 0.f, 0.f, 0.f), buf1 = buf0;
    if (isg) {
        buf0 = *(const float4*)gp;
        buf1 = *(const float4*)(gp + 80);
    }

#pragma unroll 2
    for (int t = 0; t < 1024; t++) {
        float4 cur = (t & 1) ? buf1 : buf0;
        if (isg && t + 2 < 1024) {
            float4 nb = *(const float4*)(gp + (size_t)(t + 2) * 80);
            if (t & 1) buf1 = nb; else buf0 = nb;
        }
        float aI = isg ? cur.x : 0.0f;
        float aF = isg ? cur.y : 0.0f;
        float aG = isg ? cur.z : 0.0f;
        float aO = isg ? cur.w : 0.0f;
#pragma unroll
        for (int k = 0; k < 20; k++) {
            float hv = __shfl_sync(0xffffffffu, h, k);
            aI = fmaf(wI[k], hv, aI);
            aF = fmaf(wF[k], hv, aF);
            aG = fmaf(wG[k], hv, aG);
            aO = fmaf(wO[k], hv, aO);
        }
        if (isg) {
            float ig = fsigm(aI), fg = fsigm(aF);
            float gg = ftanh(aG), og = fsigm(aO);
            c = fmaf(fg, c, ig * gg);
            h = og * ftanh(c);
        } else if (t > 0) {
            if (l == 20) {
                Ab[t - 1] = fmaxf(aI + bm0, 0.0f);
            } else if (l == 21) {
                Cb[t - 1] = (fmaxf(aI + bm1, 0.0f) + fmaxf(aF + bm2, 0.0f) * (float)t)
                            * (1.0f / 1024.0f);
            } else if (l == 22) {
                g_SIG[(size_t)b * Ssz + (t - 1)] = fsigm(aI + bsg);
            }
        }
    }

    // tail: heads for t=1023 using final h
    {
        float aI = 0.0f, aF = 0.0f;
#pragma unroll
        for (int k = 0; k < 20; k++) {
            float hv = __shfl_sync(0xffffffffu, h, k);
            aI = fmaf(wI[k], hv, aI);
            aF = fmaf(wF[k], hv, aF);
        }
        if (l == 20) Ab[1023] = fmaxf(aI + bm0, 0.0f);
        else if (l == 21) Cb[1023] = (fmaxf(aI + bm1, 0.0f) + fmaxf(aF + bm2, 0.0f) * 1024.0f)
                                     * (1.0f / 1024.0f);
        else if (l == 22) g_SIG[(size_t)b * Ssz + 1023] = fsigm(aI + bsg);
    }
    __syncwarp();

    if (l == 0) {
        float mu = 0.0f;
        float* mo = g_MU + (size_t)b * Ssz;
#pragma unroll 4
        for (int j = 0; j < 1024; j++) {
            mu = fmaf(Ab[j], mu, Cb[j]);
            mo[j] = mu;
        }
    }
}

// ================= Kernel 3: positional attention GEMM (unchanged) =================
__global__ __launch_bounds__(256, 2) void k3_attn(
    const float* __restrict__ x, float* __restrict__ out)
{
    __shared__ float xs[32 * 128];   // xs[t][d]
    __shared__ float wbuf[32 * 128]; // wbuf[t][j]
    __shared__ float muv[128], i2s[128], invj[128], nrm[128];

    int b = blockIdx.y;
    int jt = 7 - blockIdx.x;   // big tiles first
    int j0 = jt * 128;
    int tid = threadIdx.x;

    if (tid < 128) {
        int j = j0 + tid;
        float mu = g_MU[(size_t)b * Ssz + j];
        float sg = g_SIG[(size_t)b * Ssz + j];
        muv[tid] = mu;
        i2s[tid] = -1.442695041f / (2.0f * sg * sg);
        invj[tid] = 1.0f / (float)(j + 1);
        nrm[tid] = 0.0f;
    }
    __syncthreads();

    int ty = tid >> 4, tx = tid & 15;
    int jcol = tid & 127, part = tid >> 7;
    float mu_r = muv[jcol], i2s_r = i2s[jcol], invj_r = invj[jcol];
    int jabs = j0 + jcol;

    float acc[8][8];
#pragma unroll
    for (int i = 0; i < 8; i++)
#pragma unroll
        for (int j = 0; j < 8; j++) acc[i][j] = 0.0f;

    const float* xb = x + (size_t)b * Ssz * Dsz;
    int nch = (jt + 1) * 4;

    for (int tc = 0; tc < nch; tc++) {
        // stage x chunk: 32 t x 128 d
#pragma unroll
        for (int q = 0; q < 4; q++) {
            int f4 = tid + 256 * q;
            int tr = f4 >> 5, dc = (f4 & 31) << 2;
            *(float4*)&xs[tr * 128 + dc] =
                *(const float4*)(xb + (size_t)(tc * 32 + tr) * 128 + dc);
        }
        // compute weight chunk: each thread 16 t's for its j column
        float na = 0.0f;
        int tbase = part * 16;
#pragma unroll
        for (int tt = 0; tt < 16; tt++) {
            int t = tc * 32 + tbase + tt;
            float w = 0.0f;
            if (t <= jabs) {
                float r = fmaf((float)t, invj_r, -mu_r);
                w = fexp2(r * r * i2s_r);
            }
            wbuf[(tbase + tt) * 128 + jcol] = w;
            na = fmaf(w, w, na);
        }
        atomicAdd(&nrm[jcol], na);
        __syncthreads();

#pragma unroll 8
        for (int kk = 0; kk < 32; kk++) {
            float a[8], bv[8];
            float4 t0 = *(float4*)&wbuf[kk * 128 + ty * 4];
            float4 t1 = *(float4*)&wbuf[kk * 128 + 64 + ty * 4];
            a[0] = t0.x; a[1] = t0.y; a[2] = t0.z; a[3] = t0.w;
            a[4] = t1.x; a[5] = t1.y; a[6] = t1.z; a[7] = t1.w;
            float4 u0 = *(float4*)&xs[kk * 128 + tx * 4];
            float4 u1 = *(float4*)&xs[kk * 128 + 64 + tx * 4];
            bv[0] = u0.x; bv[1] = u0.y; bv[2] = u0.z; bv[3] = u0.w;
            bv[4] = u1.x; bv[5] = u1.y; bv[6] = u1.z; bv[7] = u1.w;
#pragma unroll
            for (int i = 0; i < 8; i++)
#pragma unroll
                for (int j = 0; j < 8; j++)
                    acc[i][j] = fmaf(a[i], bv[j], acc[i][j]);
        }
        __syncthreads();
    }
    __syncthreads();   // nrm fully accumulated before epilogue reads

    // epilogue: normalize rows and store
#pragma unroll
    for (int ri = 0; ri < 8; ri++) {
        int jrel = (ri < 4) ? (ty * 4 + ri) : (64 + ty * 4 + (ri - 4));
        float n = nrm[jrel];
        float s = fmaxf(sqrtf(n), 1e-12f);
        float inv = 1.0f / s;
        int j = j0 + jrel;
        float* op = out + ((size_t)b * Ssz + j) * Dsz;
        float4 v0, v1;
        v0.x = acc[ri][0] * inv; v0.y = acc[ri][1] * inv;
        v0.z = acc[ri][2] * inv; v0.w = acc[ri][3] * inv;
        v1.x = acc[ri][4] * inv; v1.y = acc[ri][5] * inv;
        v1.z = acc[ri][6] * inv; v1.w = acc[ri][7] * inv;
        *(float4*)(op + tx * 4) = v0;
        *(float4*)(op + 64 + tx * 4) = v1;
    }
}

// ================= launcher =================
extern "C" void kernel_launch(void* const* d_in, const int* in_sizes, int n_in,
                              void* d_out, int out_size)
{
    const float* x    = (const float*)d_in[0];
    const float* Wih  = (const float*)d_in[1];
    const float* Whh  = (const float*)d_in[2];
    const float* bih  = (const float*)d_in[3];
    const float* bhh  = (const float*)d_in[4];
    const float* Wmu  = (const float*)d_in[5];
    const float* bmu  = (const float*)d_in[6];
    const float* Wsig = (const float*)d_in[7];
    const float* bsig = (const float*)d_in[8];
    float* out = (float*)d_out;

    k1_gi<<<(Bsz * Ssz) / 64, 320>>>(x, Wih, bih, bhh);
    k2_lstm<<<Bsz, 32>>>(Whh, Wmu, bmu, Wsig, bsig);
    dim3 g3(8, Bsz);
    k3_attn<<<g3, 256>>>(x, out);
}

// round 5
// speedup vs baseline: 1.2223x; 1.1072x over previous
#include <cuda_runtime.h>
#include <cuda_bf16.h>
#include <cstdint>

#define Bsz 64
#define Ssz 1024
#define Dsz 128
#define Hsz 20
#define Gsz 80

// scratch (static device globals: no allocation)
__device__ float g_GI[Bsz * Ssz * Gsz];   // permuted: [b][t][u*4+type]
__device__ float g_MU[Bsz * Ssz];
__device__ float g_SIG[Bsz * Ssz];
__device__ __nv_bfloat16 g_XHT[Bsz * Dsz * Ssz];  // x^T hi  [b][d][t]
__device__ __nv_bfloat16 g_XLT[Bsz * Dsz * Ssz];  // x^T lo  [b][d][t]

// ---------------- fast math helpers ----------------
__device__ __forceinline__ float fexp2(float x) {
    float r; asm("ex2.approx.ftz.f32 %0, %1;" : "=f"(r) : "f"(x)); return r;
}
__device__ __forceinline__ float frcp(float x) {
    float r; asm("rcp.approx.ftz.f32 %0, %1;" : "=f"(r) : "f"(x)); return r;
}
__device__ __forceinline__ float fsigm(float x) {
    return frcp(1.0f + fexp2(-1.442695041f * x));
}
__device__ __forceinline__ float ftanh(float x) {
    x = fminf(fmaxf(x, -10.0f), 10.0f);
    float e = fexp2(2.885390082f * x);
    return (e - 1.0f) * frcp(e + 1.0f);
}

__device__ __forceinline__ void ldm4(uint32_t& r0, uint32_t& r1, uint32_t& r2, uint32_t& r3,
                                     uint32_t saddr) {
    asm volatile("ldmatrix.sync.aligned.m8n8.x4.shared.b16 {%0,%1,%2,%3}, [%4];"
                 : "=r"(r0), "=r"(r1), "=r"(r2), "=r"(r3) : "r"(saddr));
}
__device__ __forceinline__ void mma16816(float* d,
                                         uint32_t a0, uint32_t a1, uint32_t a2, uint32_t a3,
                                         uint32_t b0, uint32_t b1) {
    asm volatile("mma.sync.aligned.m16n8k16.row.col.f32.bf16.bf16.f32 "
                 "{%0,%1,%2,%3}, {%4,%5,%6,%7}, {%8,%9}, {%0,%1,%2,%3};"
                 : "+f"(d[0]), "+f"(d[1]), "+f"(d[2]), "+f"(d[3])
                 : "r"(a0), "r"(a1), "r"(a2), "r"(a3), "r"(b0), "r"(b1));
}

// ================= Kernel 0: split+transpose x -> g_XHT/g_XLT [b][d][t] ==========
__global__ __launch_bounds__(256) void k0_split(const float* __restrict__ x)
{
    __shared__ float xs[32 * 128];
    int b = blockIdx.y, t0 = blockIdx.x * 32;
    int tid = threadIdx.x;
    const float* xb = x + ((size_t)b * Ssz + t0) * Dsz;
#pragma unroll
    for (int q = 0; q < 4; q++) {
        int idx = tid + 256 * q;
        int r = idx >> 5, c4 = (idx & 31) << 2;
        *(float4*)&xs[r * 128 + c4] = *(const float4*)(xb + (size_t)r * 128 + c4);
    }
    __syncthreads();
    int d = tid >> 1, tseg = (tid & 1) * 16;
    __nv_bfloat16 h16[16], l16[16];
#pragma unroll
    for (int tt = 0; tt < 16; tt++) {
        float v = xs[(tseg + tt) * 128 + d];
        __nv_bfloat16 h = __float2bfloat16_rn(v);
        h16[tt] = h;
        l16[tt] = __float2bfloat16_rn(v - __bfloat162float(h));
    }
    size_t off = ((size_t)b * 128 + d) * 1024 + t0 + tseg;
    *(uint4*)(g_XHT + off) = *(uint4*)&h16[0];
    *(uint4*)(g_XHT + off + 8) = *(uint4*)&h16[8];
    *(uint4*)(g_XLT + off) = *(uint4*)&l16[0];
    *(uint4*)(g_XLT + off + 8) = *(uint4*)&l16[8];
}

// ================= Kernel 1: GI = x @ W_ih^T + bias (permuted) =================
__global__ __launch_bounds__(320) void k1_gi(
    const float* __restrict__ x,
    const float* __restrict__ Wih,
    const float* __restrict__ bih,
    const float* __restrict__ bhh)
{
    __shared__ __align__(16) float ws[128 * 80];
    __shared__ __align__(16) float xs[16 * 64];
    __shared__ __align__(16) float bs[80];

    int tid = threadIdx.x;
    for (int i = tid; i < Gsz * 32; i += 320) {
        int g = i >> 5, k4 = (i & 31) << 2;
        int p = (g % 20) * 4 + (g / 20);
        float4 v = *(const float4*)(Wih + g * 128 + k4);
        ws[(k4 + 0) * 80 + p] = v.x;
        ws[(k4 + 1) * 80 + p] = v.y;
        ws[(k4 + 2) * 80 + p] = v.z;
        ws[(k4 + 3) * 80 + p] = v.w;
    }
    if (tid < 80) {
        int p = (tid % 20) * 4 + (tid / 20);
        bs[p] = bih[tid] + bhh[tid];
    }

    int row0 = blockIdx.x * 64;
    int tx = tid % 20, ty = tid / 20;
    float acc[4][4];
#pragma unroll
    for (int r = 0; r < 4; r++)
#pragma unroll
        for (int c = 0; c < 4; c++) acc[r][c] = 0.0f;

    for (int kc = 0; kc < 8; kc++) {
        __syncthreads();
        if (tid < 256) {
            int r = tid >> 2, kk = (tid & 3) << 2;
            float4 v = *(const float4*)(x + (size_t)(row0 + r) * 128 + kc * 16 + kk);
            xs[(kk + 0) * 64 + r] = v.x;
            xs[(kk + 1) * 64 + r] = v.y;
            xs[(kk + 2) * 64 + r] = v.z;
            xs[(kk + 3) * 64 + r] = v.w;
        }
        __syncthreads();
#pragma unroll
        for (int kk = 0; kk < 16; kk++) {
            float4 xa = *(float4*)&xs[kk * 64 + ty * 4];
            float4 wv = *(float4*)&ws[(kc * 16 + kk) * 80 + tx * 4];
            acc[0][0] = fmaf(xa.x, wv.x, acc[0][0]);
            acc[0][1] = fmaf(xa.x, wv.y, acc[0][1]);
            acc[0][2] = fmaf(xa.x, wv.z, acc[0][2]);
            acc[0][3] = fmaf(xa.x, wv.w, acc[0][3]);
            acc[1][0] = fmaf(xa.y, wv.x, acc[1][0]);
            acc[1][1] = fmaf(xa.y, wv.y, acc[1][1]);
            acc[1][2] = fmaf(xa.y, wv.z, acc[1][2]);
            acc[1][3] = fmaf(xa.y, wv.w, acc[1][3]);
            acc[2][0] = fmaf(xa.z, wv.x, acc[2][0]);
            acc[2][1] = fmaf(xa.z, wv.y, acc[2][1]);
            acc[2][2] = fmaf(xa.z, wv.z, acc[2][2]);
            acc[2][3] = fmaf(xa.z, wv.w, acc[2][3]);
            acc[3][0] = fmaf(xa.w, wv.x, acc[3][0]);
            acc[3][1] = fmaf(xa.w, wv.y, acc[3][1]);
            acc[3][2] = fmaf(xa.w, wv.z, acc[3][2]);
            acc[3][3] = fmaf(xa.w, wv.w, acc[3][3]);
        }
    }
    float4 bb = *(float4*)&bs[tx * 4];
    float* go = g_GI + (size_t)row0 * 80;
#pragma unroll
    for (int r = 0; r < 4; r++) {
        int row = ty * 4 + r;
        float4 o;
        o.x = acc[r][0] + bb.x;
        o.y = acc[r][1] + bb.y;
        o.z = acc[r][2] + bb.z;
        o.w = acc[r][3] + bb.w;
        *(float4*)&go[(size_t)row * 80 + tx * 4] = o;
    }
}

// ================= Kernel 2: warp-per-batch shuffle LSTM (unchanged) ==============
__global__ __launch_bounds__(32) void k2_lstm(
    const float* __restrict__ Whh,
    const float* __restrict__ Wmu, const float* __restrict__ bmu,
    const float* __restrict__ Wsig, const float* __restrict__ bsig)
{
    __shared__ float Ab[1024];
    __shared__ float Cb[1024];

    int b = blockIdx.x;
    int l = threadIdx.x;
    bool isg = (l < 20);

    float wI[20], wF[20], wG[20], wO[20];
#pragma unroll
    for (int k = 0; k < 20; k++) { wI[k] = 0.f; wF[k] = 0.f; wG[k] = 0.f; wO[k] = 0.f; }
    if (isg) {
#pragma unroll
        for (int k = 0; k < 20; k++) {
            wI[k] = Whh[l * 20 + k];
            wF[k] = Whh[(20 + l) * 20 + k];
            wG[k] = Whh[(40 + l) * 20 + k];
            wO[k] = Whh[(60 + l) * 20 + k];
        }
    } else if (l == 20) {
#pragma unroll
        for (int k = 0; k < 20; k++) wI[k] = Wmu[k];
    } else if (l == 21) {
#pragma unroll
        for (int k = 0; k < 20; k++) { wI[k] = Wmu[20 + k]; wF[k] = Wmu[40 + k]; }
    } else if (l == 22) {
#pragma unroll
        for (int k = 0; k < 20; k++) wI[k] = Wsig[k];
    }
    float bm0 = bmu[0], bm1 = bmu[1], bm2 = bmu[2], bsg = bsig[0];

    float h = 0.0f, c = 0.0f;
    const float* gp = g_GI + (size_t)b * Ssz * Gsz + l * 4;

    float4 buf0 = make_float4(0.f, 0.f, 0.f, 0.f), buf1 = buf0;
    if (isg) {
        buf0 = *(const float4*)gp;
        buf1 = *(const float4*)(gp + 80);
    }

#pragma unroll 2
    for (int t = 0; t < 1024; t++) {
        float4 cur = (t & 1) ? buf1 : buf0;
        if (isg && t + 2 < 1024) {
            float4 nb = *(const float4*)(gp + (size_t)(t + 2) * 80);
            if (t & 1) buf1 = nb; else buf0 = nb;
        }
        float aI = isg ? cur.x : 0.0f;
        float aF = isg ? cur.y : 0.0f;
        float aG = isg ? cur.z : 0.0f;
        float aO = isg ? cur.w : 0.0f;
#pragma unroll
        for (int k = 0; k < 20; k++) {
            float hv = __shfl_sync(0xffffffffu, h, k);
            aI = fmaf(wI[k], hv, aI);
            aF = fmaf(wF[k], hv, aF);
            aG = fmaf(wG[k], hv, aG);
            aO = fmaf(wO[k], hv, aO);
        }
        if (isg) {
            float ig = fsigm(aI), fg = fsigm(aF);
            float gg = ftanh(aG), og = fsigm(aO);
            c = fmaf(fg, c, ig * gg);
            h = og * ftanh(c);
        } else if (t > 0) {
            if (l == 20) {
                Ab[t - 1] = fmaxf(aI + bm0, 0.0f);
            } else if (l == 21) {
                Cb[t - 1] = (fmaxf(aI + bm1, 0.0f) + fmaxf(aF + bm2, 0.0f) * (float)t)
                            * (1.0f / 1024.0f);
            } else if (l == 22) {
                g_SIG[(size_t)b * Ssz + (t - 1)] = fsigm(aI + bsg);
            }
        }
    }
    {
        float aI = 0.0f, aF = 0.0f;
#pragma unroll
        for (int k = 0; k < 20; k++) {
            float hv = __shfl_sync(0xffffffffu, h, k);
            aI = fmaf(wI[k], hv, aI);
            aF = fmaf(wF[k], hv, aF);
        }
        if (l == 20) Ab[1023] = fmaxf(aI + bm0, 0.0f);
        else if (l == 21) Cb[1023] = (fmaxf(aI + bm1, 0.0f) + fmaxf(aF + bm2, 0.0f) * 1024.0f)
                                     * (1.0f / 1024.0f);
        else if (l == 22) g_SIG[(size_t)b * Ssz + 1023] = fsigm(aI + bsg);
    }
    __syncwarp();

    if (l == 0) {
        float mu = 0.0f;
        float* mo = g_MU + (size_t)b * Ssz;
#pragma unroll 4
        for (int j = 0; j < 1024; j++) {
            mu = fmaf(Ab[j], mu, Cb[j]);
            mo[j] = mu;
        }
    }
}

// ================= Kernel 3: positional attention via bf16 tensor-core MMA ========
// 3-way split: out = wh*xh + wh*xl + wl*xh (fp32 accumulate). Norms in exact fp32.
// CTA: (b, 128-j tile). 8 warps, warp w owns j rows [w*16, w*16+16), all 128 d.
#define TP 40   // smem row pitch in bf16 (conflict-free ldmatrix)
__global__ __launch_bounds__(256, 2) void k3_attn(float* __restrict__ out)
{
    __shared__ __align__(16) __nv_bfloat16 xsh[128 * TP];
    __shared__ __align__(16) __nv_bfloat16 xsl[128 * TP];
    __shared__ __align__(16) __nv_bfloat16 wsh[128 * TP];
    __shared__ __align__(16) __nv_bfloat16 wsl[128 * TP];
    __shared__ float muv[128], i2s[128], invj[128], nrm[128];

    int b = blockIdx.y;
    int jt = 7 - blockIdx.x;
    int j0 = jt * 128;
    int tid = threadIdx.x;
    int warp = tid >> 5, lane = tid & 31;

    if (tid < 128) {
        int j = j0 + tid;
        float mu = g_MU[(size_t)b * Ssz + j];
        float sg = g_SIG[(size_t)b * Ssz + j];
        muv[tid] = mu;
        i2s[tid] = -1.442695041f / (2.0f * sg * sg);
        invj[tid] = 1.0f / (float)(j + 1);
        nrm[tid] = 0.0f;
    }
    __syncthreads();

    int jcol = tid & 127, part = tid >> 7;
    float mu_r = muv[jcol], i2s_r = i2s[jcol], invj_r = invj[jcol];
    int jabs = j0 + jcol;

    float acc[16][4];
#pragma unroll
    for (int i = 0; i < 16; i++)
#pragma unroll
        for (int k = 0; k < 4; k++) acc[i][k] = 0.0f;

    const __nv_bfloat16* xhb = g_XHT + (size_t)b * Dsz * Ssz;
    const __nv_bfloat16* xlb = g_XLT + (size_t)b * Dsz * Ssz;

    // smem 32-bit addresses for ldmatrix
    uint32_t xsh_s = (uint32_t)__cvta_generic_to_shared(xsh);
    uint32_t xsl_s = (uint32_t)__cvta_generic_to_shared(xsl);
    uint32_t wsh_s = (uint32_t)__cvta_generic_to_shared(wsh);
    uint32_t wsl_s = (uint32_t)__cvta_generic_to_shared(wsl);

    int nch = (jt + 1) * 4;
    for (int tc = 0; tc < nch; tc++) {
        int t0 = tc * 32;
        // issue global loads for x tiles (each thread: 2x uint4 per split)
        uint4 gh[2], gl[2];
        int rows[2], qs[2];
#pragma unroll
        for (int q2 = 0; q2 < 2; q2++) {
            int idx = tid * 2 + q2;
            int row = idx >> 2, qq = idx & 3;
            rows[q2] = row; qs[q2] = qq;
            size_t off = (size_t)row * 1024 + t0 + qq * 8;
            gh[q2] = *(const uint4*)(xhb + off);
            gl[q2] = *(const uint4*)(xlb + off);
        }
        // compute + split weights while loads are in flight
        float na = 0.0f;
        int tbase = part * 16;
#pragma unroll
        for (int tt = 0; tt < 16; tt++) {
            int t = t0 + tbase + tt;
            float w = 0.0f;
            if (t <= jabs) {
                float r = fmaf((float)t, invj_r, -mu_r);
                w = fexp2(r * r * i2s_r);
            }
            __nv_bfloat16 wh = __float2bfloat16_rn(w);
            wsh[jcol * TP + tbase + tt] = wh;
            wsl[jcol * TP + tbase + tt] = __float2bfloat16_rn(w - __bfloat162float(wh));
            na = fmaf(w, w, na);
        }
        atomicAdd(&nrm[jcol], na);
        // store staged x tiles
#pragma unroll
        for (int q2 = 0; q2 < 2; q2++) {
            *(uint4*)&xsh[rows[q2] * TP + qs[q2] * 8] = gh[q2];
            *(uint4*)&xsl[rows[q2] * TP + qs[q2] * 8] = gl[q2];
        }
        __syncthreads();

        // A fragments (w): 2 k-steps x 2 splits
        uint32_t ah[2][4], al[2][4];
        {
            int ar = warp * 16 + (lane & 7) + ((lane >> 3) & 1) * 8;
#pragma unroll
            for (int s = 0; s < 2; s++) {
                int at = s * 16 + (lane >> 4) * 8;
                uint32_t off = (uint32_t)(ar * TP + at) * 2;
                ldm4(ah[s][0], ah[s][1], ah[s][2], ah[s][3], wsh_s + off);
                ldm4(al[s][0], al[s][1], al[s][2], al[s][3], wsl_s + off);
            }
        }
        // B fragments + MMAs over 8 d-pairs x 2 k-steps
#pragma unroll
        for (int p = 0; p < 8; p++) {
#pragma unroll
            for (int s = 0; s < 2; s++) {
                int br = p * 16 + (lane & 7) + (lane >> 4) * 8;
                int bt = s * 16 + ((lane >> 3) & 1) * 8;
                uint32_t off = (uint32_t)(br * TP + bt) * 2;
                uint32_t bh0, bh1, bh2, bh3, bl0, bl1, bl2, bl3;
                ldm4(bh0, bh1, bh2, bh3, xsh_s + off);
                ldm4(bl0, bl1, bl2, bl3, xsl_s + off);
                // hi*hi
                mma16816(acc[2 * p],     ah[s][0], ah[s][1], ah[s][2], ah[s][3], bh0, bh1);
                mma16816(acc[2 * p + 1], ah[s][0], ah[s][1], ah[s][2], ah[s][3], bh2, bh3);
                // hi*lo
                mma16816(acc[2 * p],     ah[s][0], ah[s][1], ah[s][2], ah[s][3], bl0, bl1);
                mma16816(acc[2 * p + 1], ah[s][0], ah[s][1], ah[s][2], ah[s][3], bl2, bl3);
                // lo*hi
                mma16816(acc[2 * p],     al[s][0], al[s][1], al[s][2], al[s][3], bh0, bh1);
                mma16816(acc[2 * p + 1], al[s][0], al[s][1], al[s][2], al[s][3], bh2, bh3);
            }
        }
        __syncthreads();
    }

    // epilogue: normalize rows, store
    int r0 = warp * 16 + (lane >> 2);
    int r1 = r0 + 8;
    float n0 = nrm[r0], n1 = nrm[r1];
    float inv0 = frcp(fmaxf(sqrtf(n0), 1e-12f));
    float inv1 = frcp(fmaxf(sqrtf(n1), 1e-12f));
    float* o0 = out + ((size_t)b * Ssz + j0 + r0) * Dsz;
    float* o1 = out + ((size_t)b * Ssz + j0 + r1) * Dsz;
    int dc = (lane & 3) * 2;
#pragma unroll
    for (int nt = 0; nt < 16; nt++) {
        int d = nt * 8 + dc;
        float2 v0 = make_float2(acc[nt][0] * inv0, acc[nt][1] * inv0);
        float2 v1 = make_float2(acc[nt][2] * inv1, acc[nt][3] * inv1);
        *(float2*)(o0 + d) = v0;
        *(float2*)(o1 + d) = v1;
    }
}

// ================= launcher =================
extern "C" void kernel_launch(void* const* d_in, const int* in_sizes, int n_in,
                              void* d_out, int out_size)
{
    const float* x    = (const float*)d_in[0];
    const float* Wih  = (const float*)d_in[1];
    const float* Whh  = (const float*)d_in[2];
    const float* bih  = (const float*)d_in[3];
    const float* bhh  = (const float*)d_in[4];
    const float* Wmu  = (const float*)d_in[5];
    const float* bmu  = (const float*)d_in[6];
    const float* Wsig = (const float*)d_in[7];
    const float* bsig = (const float*)d_in[8];
    float* out = (float*)d_out;

    dim3 g0(Ssz / 32, Bsz);
    k0_split<<<g0, 256>>>(x);
    k1_gi<<<(Bsz * Ssz) / 64, 320>>>(x, Wih, bih, bhh);
    k2_lstm<<<Bsz, 32>>>(Whh, Wmu, bmu, Wsig, bsig);
    dim3 g3(8, Bsz);
    k3_attn<<<g3, 256>>>(out);
}